// round 9
// baseline (speedup 1.0000x reference)
#include <cuda_runtime.h>
#include <math.h>
#include <stdint.h>

// Problem constants (fixed shapes from reference)
#define DIN    512
#define BGRAPH 1024
#define NGATE  2048   // 4*DIN
#define KDIM   1024   // 2*DIN  (state S = [h | r])
#define TSTEPS 6
#define EMAXN  (1 << 17)

// ---------------- scratch (device globals; no allocation allowed) ----------
__device__ float g_Wcomb[NGATE * KDIM];   // 8 MB   combined LSTM weight
__device__ float g_bsum[NGATE];
__device__ float g_S[BGRAPH * KDIM];      // 4 MB   [h | r] state
__device__ float g_c[BGRAPH * DIN];       // 2 MB   cell state
__device__ float g_z[BGRAPH * NGATE];     // 8 MB   pre-activation gates
__device__ float g_e[EMAXN];              // attention logits scratch
__device__ int   g_seg[BGRAPH + 1];       // segment boundaries

// ---------------- prep kernels ---------------------------------------------
__global__ void prep_w_kernel(const float* __restrict__ Wih,
                              const float* __restrict__ Whh,
                              float* __restrict__ Wcomb) {
    int idx = blockIdx.x * 256 + threadIdx.x;       // < 2048*1024
    int rr = idx >> 10, cc = idx & 1023;
    float v = Wih[idx];                              // Wih row stride = 1024
    if (cc < DIN) v += Whh[rr * DIN + cc];
    Wcomb[idx] = v;
}

__global__ void prep_b_kernel(const float* __restrict__ bih,
                              const float* __restrict__ bhh,
                              float* __restrict__ bsum) {
    int idx = blockIdx.x * 256 + threadIdx.x;
    if (idx < NGATE) bsum[idx] = bih[idx] + bhh[idx];
}

// batch may arrive as int32 (JAX default, no x64) or genuine int64.
// Detect on-device: int32 view word [n-1] is 0 for little-endian int64 data
// (high word of a value < 2^31), but equals batch[n-1] (~1023, sorted) for
// int32 data. Then lower_bound per graph id.
__global__ void seg_kernel(const void* __restrict__ batchv, int n,
                           int* __restrict__ seg) {
    const int*       w32 = (const int*)batchv;
    const long long* w64 = (const long long*)batchv;
    const bool is64 = (w32[n - 1] == 0);
    int b = blockIdx.x * 256 + threadIdx.x;
    if (b > BGRAPH) return;
    int lo = 0, hi = n;                              // lower_bound(batch, b)
    while (lo < hi) {
        int mid = (lo + hi) >> 1;
        long long v = is64 ? w64[mid] : (long long)w32[mid];
        if (v < (long long)b) lo = mid + 1; else hi = mid;
    }
    seg[b] = lo;
}

__global__ void init_zero_kernel(float* __restrict__ S, float* __restrict__ c) {
    int idx = blockIdx.x * 256 + threadIdx.x;        // < 1.5M
    if (idx < BGRAPH * KDIM) S[idx] = 0.f;
    else                     c[idx - BGRAPH * KDIM] = 0.f;
}

// ---------------- SGEMM with FFMA2 (fma.rn.f32x2) --------------------------
// C[M,N] = A[M,K] @ B[N,K]^T + bias[N]   (optional ReLU)
// Tile: 64(M) x 128(N) x 8(K); 256 threads, each computes 4x8 outputs.
#define BM 64
#define BN 128
#define BKK 8
#define TM 4
#define TN 8

template <bool RELU>
__global__ __launch_bounds__(256, 2)
void sgemm_bias_kernel(const float* __restrict__ A, const float* __restrict__ Bm,
                       const float* __restrict__ bias, float* __restrict__ C,
                       int M, int N, int K) {
    __shared__ float As[BKK][BM];
    __shared__ float Bs[BKK][BN];
    const int tid  = threadIdx.x;
    const int bm   = blockIdx.y * BM;
    const int bn   = blockIdx.x * BN;
    const int tx   = tid & 15;            // 16 col groups (x TN=8 -> 128)
    const int ty   = tid >> 4;            // 16 row groups (x TM=4 -> 64)
    // A-tile loader: 64 rows x 8 cols = 512 floats / 256 thr = float2 each
    const int arow = tid >> 2;            // 0..63
    const int acol = (tid & 3) * 2;       // 0,2,4,6
    // B-tile loader: 128 rows x 8 cols = 1024 floats / 256 thr = float4 each
    const int brow = tid >> 1;            // 0..127
    const int bcol = (tid & 1) * 4;       // 0 or 4

    unsigned long long acc[TM][TN / 2] = {};   // packed f32x2 accumulators

    const float* Aptr = A  + (size_t)(bm + arow) * K + acol;
    const float* Bptr = Bm + (size_t)(bn + brow) * K + bcol;

    for (int k0 = 0; k0 < K; k0 += BKK) {
        float2 a2 = *(const float2*)(Aptr + k0);
        float4 b4 = *(const float4*)(Bptr + k0);
        As[acol + 0][arow] = a2.x; As[acol + 1][arow] = a2.y;
        Bs[bcol + 0][brow] = b4.x; Bs[bcol + 1][brow] = b4.y;
        Bs[bcol + 2][brow] = b4.z; Bs[bcol + 3][brow] = b4.w;
        __syncthreads();
#pragma unroll
        for (int k = 0; k < BKK; k++) {
            float ra[TM], rb[TN];
#pragma unroll
            for (int i = 0; i < TM; i++) ra[i] = As[k][ty * TM + i];
#pragma unroll
            for (int j = 0; j < TN; j++) rb[j] = Bs[k][tx * TN + j];
            unsigned long long bp[TN / 2];
#pragma unroll
            for (int j = 0; j < TN / 2; j++)
                asm("mov.b64 %0, {%1, %2};" : "=l"(bp[j])
                    : "r"(__float_as_uint(rb[2 * j])), "r"(__float_as_uint(rb[2 * j + 1])));
#pragma unroll
            for (int i = 0; i < TM; i++) {
                unsigned long long ap;
                asm("mov.b64 %0, {%1, %1};" : "=l"(ap) : "r"(__float_as_uint(ra[i])));
#pragma unroll
                for (int j = 0; j < TN / 2; j++)
                    asm("fma.rn.f32x2 %0, %1, %2, %0;"
                        : "+l"(acc[i][j]) : "l"(ap), "l"(bp[j]));
            }
        }
        __syncthreads();
    }

#pragma unroll
    for (int i = 0; i < TM; i++) {
        int m = bm + ty * TM + i;
        float* crow = C + (size_t)m * N + bn + tx * TN;
#pragma unroll
        for (int j = 0; j < TN / 2; j++) {
            unsigned lo, hi;
            asm("mov.b64 {%0, %1}, %2;" : "=r"(lo), "=r"(hi) : "l"(acc[i][j]));
            float v0 = __uint_as_float(lo) + bias[bn + tx * TN + 2 * j];
            float v1 = __uint_as_float(hi) + bias[bn + tx * TN + 2 * j + 1];
            if (RELU) { v0 = fmaxf(v0, 0.f); v1 = fmaxf(v1, 0.f); }
            *(float2*)(crow + 2 * j) = make_float2(v0, v1);
        }
    }
}

// ---------------- LSTM cell elementwise ------------------------------------
__global__ __launch_bounds__(256)
void lstm_kernel(const float* __restrict__ z, float* __restrict__ c,
                 float* __restrict__ S) {
    int idx = blockIdx.x * 256 + threadIdx.x;   // < 1024*512
    int m = idx >> 9, d = idx & 511;
    const float* zr = z + (size_t)m * NGATE;
    float zi = zr[d], zf = zr[DIN + d], zg = zr[2 * DIN + d], zo = zr[3 * DIN + d];
    float si = 1.f / (1.f + __expf(-zi));
    float sf = 1.f / (1.f + __expf(-zf));
    float so = 1.f / (1.f + __expf(-zo));
    float cn = sf * c[idx] + si * tanhf(zg);
    c[idx] = cn;
    S[(size_t)m * KDIM + d] = so * tanhf(cn);   // h -> left half of S
}

// ---------------- fused segment softmax attention (one block per graph) ----
__global__ __launch_bounds__(256)
void attn_kernel(const float* __restrict__ x, float* __restrict__ S,
                 const int* __restrict__ seg, float* __restrict__ escr) {
    __shared__ float  sq[DIN];
    __shared__ float4 sred[8 * 128];   // 16 KB: 8 warps x 512-dim partials
    __shared__ float  swmax[8];
    __shared__ float  swden[8];
    __shared__ float  sgmax;

    const int b = blockIdx.x;
    const int tid = threadIdx.x;
    const int w = tid >> 5, lane = tid & 31;
    const int s = seg[b];
    const int e = seg[b + 1];

    for (int d = tid; d < DIN; d += 256) sq[d] = S[(size_t)b * KDIM + d];  // q = h
    __syncthreads();

    const float4* q4 = (const float4*)sq;
    const float4 qa = q4[lane], qb = q4[32 + lane], qc = q4[64 + lane], qd = q4[96 + lane];

    // Phase A: logits + segment max (warp per node)
    float wmax = -INFINITY;
    for (int n = s + w; n < e; n += 8) {
        const float4* xv = (const float4*)(x + (size_t)n * DIN);
        float4 xa = xv[lane], xb = xv[32 + lane], xc = xv[64 + lane], xd = xv[96 + lane];
        float p = xa.x * qa.x + xa.y * qa.y + xa.z * qa.z + xa.w * qa.w;
        p += xb.x * qb.x + xb.y * qb.y + xb.z * qb.z + xb.w * qb.w;
        p += xc.x * qc.x + xc.y * qc.y + xc.z * qc.z + xc.w * qc.w;
        p += xd.x * qd.x + xd.y * qd.y + xd.z * qd.z + xd.w * qd.w;
#pragma unroll
        for (int off = 16; off > 0; off >>= 1)
            p += __shfl_xor_sync(0xffffffffu, p, off);
        if (lane == 0) escr[n] = p;
        wmax = fmaxf(wmax, p);
    }
    if (lane == 0) swmax[w] = wmax;
    __syncthreads();
    if (tid == 0) {
        float m = -INFINITY;
#pragma unroll
        for (int i = 0; i < 8; i++) m = fmaxf(m, swmax[i]);
        sgmax = m;
    }
    __syncthreads();
    const float gmax = sgmax;

    // Phase B: exp, denom, weighted sum (x re-read mostly hits L2)
    float4 aa = make_float4(0, 0, 0, 0), ab = aa, ac = aa, ad = aa;
    float den = 0.f;
    for (int n = s + w; n < e; n += 8) {
        float ex = __expf(escr[n] - gmax);
        const float4* xv = (const float4*)(x + (size_t)n * DIN);
        float4 xa = xv[lane], xb = xv[32 + lane], xc = xv[64 + lane], xd = xv[96 + lane];
        aa.x += ex * xa.x; aa.y += ex * xa.y; aa.z += ex * xa.z; aa.w += ex * xa.w;
        ab.x += ex * xb.x; ab.y += ex * xb.y; ab.z += ex * xb.z; ab.w += ex * xb.w;
        ac.x += ex * xc.x; ac.y += ex * xc.y; ac.z += ex * xc.z; ac.w += ex * xc.w;
        ad.x += ex * xd.x; ad.y += ex * xd.y; ad.z += ex * xd.z; ad.w += ex * xd.w;
        den += ex;
    }
    sred[w * 128 + lane]      = aa;
    sred[w * 128 + 32 + lane] = ab;
    sred[w * 128 + 64 + lane] = ac;
    sred[w * 128 + 96 + lane] = ad;
    if (lane == 0) swden[w] = den;
    __syncthreads();

    if (tid < 128) {
        float4 t = make_float4(0, 0, 0, 0);
#pragma unroll
        for (int ww = 0; ww < 8; ww++) {
            float4 v = sred[ww * 128 + tid];
            t.x += v.x; t.y += v.y; t.z += v.z; t.w += v.w;
        }
        float dtot = 0.f;
#pragma unroll
        for (int i = 0; i < 8; i++) dtot += swden[i];
        float inv = (e > s) ? (1.0f / dtot) : 0.f;   // empty segment -> r = 0
        t.x *= inv; t.y *= inv; t.z *= inv; t.w *= inv;
        ((float4*)(S + (size_t)b * KDIM + DIN))[tid] = t;  // r -> right half of S
    }
}

// ---------------- launch ----------------------------------------------------
extern "C" void kernel_launch(void* const* d_in, const int* in_sizes, int n_in,
                              void* d_out, int out_size) {
    const float* x     = (const float*)d_in[0];
    const void*  batch = d_in[1];                 // int32 OR int64 (detected on device)
    const float* Wih   = (const float*)d_in[2];
    const float* Whh   = (const float*)d_in[3];
    const float* bih   = (const float*)d_in[4];
    const float* bhh   = (const float*)d_in[5];
    const float* Wpost = (const float*)d_in[6];
    const float* bpost = (const float*)d_in[7];
    float*       out   = (float*)d_out;
    const int N = in_sizes[1];   // node count (100000)

    float *S, *c, *z, *Wcomb, *bsum, *e;
    int* seg;
    cudaGetSymbolAddress((void**)&S,     g_S);
    cudaGetSymbolAddress((void**)&c,     g_c);
    cudaGetSymbolAddress((void**)&z,     g_z);
    cudaGetSymbolAddress((void**)&Wcomb, g_Wcomb);
    cudaGetSymbolAddress((void**)&bsum,  g_bsum);
    cudaGetSymbolAddress((void**)&e,     g_e);
    cudaGetSymbolAddress((void**)&seg,   g_seg);

    prep_w_kernel<<<(NGATE * KDIM) / 256, 256>>>(Wih, Whh, Wcomb);
    prep_b_kernel<<<NGATE / 256, 256>>>(bih, bhh, bsum);
    seg_kernel<<<(BGRAPH + 1 + 255) / 256, 256>>>(batch, N, seg);
    init_zero_kernel<<<(BGRAPH * KDIM + BGRAPH * DIN) / 256, 256>>>(S, c);

    for (int t = 0; t < TSTEPS; t++) {
        // z = S @ Wcomb^T + bsum   (M=1024, N=2048, K=1024) -> 16x16 = 256 CTAs
        sgemm_bias_kernel<false><<<dim3(NGATE / BN, BGRAPH / BM), 256>>>(
            S, Wcomb, bsum, z, BGRAPH, NGATE, KDIM);
        lstm_kernel<<<(BGRAPH * DIN) / 256, 256>>>(z, c, S);
        attn_kernel<<<BGRAPH, 256>>>(x, S, seg, e);
    }
    // out = relu(S @ Wpost^T + bpost)   (M=1024, N=512, K=1024) -> 4x16 = 64 CTAs
    sgemm_bias_kernel<true><<<dim3(DIN / BN, BGRAPH / BM), 256>>>(
        S, Wpost, bpost, out, BGRAPH, DIN, KDIM);
}

// round 11
// speedup vs baseline: 2.3892x; 2.3892x over previous
#include <cuda_runtime.h>
#include <cuda_bf16.h>
#include <math.h>
#include <stdint.h>

// Problem constants (fixed shapes from reference)
#define DIN    512
#define BGRAPH 1024
#define NGATE  2048   // 4*DIN
#define KDIM   1024   // 2*DIN  (state S = [h | r])
#define TSTEPS 6
#define EMAXN  (1 << 17)
#define KCAT   3072   // bf16x3 concatenated K

// ---------------- scratch (device globals; no allocation allowed) ----------
__device__ float g_bsum[NGATE];
__device__ float g_S[BGRAPH * KDIM];      // 4 MB  [h | r] state (fp32)
__device__ float g_c[BGRAPH * DIN];       // 2 MB  cell state
__device__ float g_z[BGRAPH * NGATE];     // 8 MB  pre-activation gates
__device__ float g_e[EMAXN];              // attention logits scratch
__device__ int   g_seg[BGRAPH + 1];       // segment boundaries
// Plain row-major bf16 split-cat operands [rows][3072]:
__device__ __align__(128) __nv_bfloat16 g_Aext[BGRAPH * KCAT];  // 6 MB
__device__ __align__(128) __nv_bfloat16 g_Bext[NGATE * KCAT];   // 12 MB
__device__ __align__(128) __nv_bfloat16 g_Pext[DIN * KCAT];     // 3 MB

// ---------------- helpers ---------------------------------------------------
__device__ __forceinline__ uint32_t smem_u32(const void* p) {
    uint32_t a;
    asm("{ .reg .u64 t; cvta.to.shared.u64 t, %1; cvt.u32.u64 %0, t; }"
        : "=r"(a) : "l"(p));
    return a;
}
__device__ __forceinline__ uint32_t sw128(uint32_t off) {
    return off ^ ((off >> 3) & 0x70);
}
__device__ __forceinline__ void cp16(uint32_t dst, const void* src) {
    asm volatile("cp.async.cg.shared.global [%0], [%1], 16;"
                 :: "r"(dst), "l"(src));
}
#define CP_COMMIT() asm volatile("cp.async.commit_group;")
#define CP_WAIT1()  asm volatile("cp.async.wait_group 1;")
#define CP_WAIT0()  asm volatile("cp.async.wait_group 0;")
#define LDSM_X4(r0, r1, r2, r3, addr) \
    asm volatile("ldmatrix.sync.aligned.m8n8.x4.shared.b16 {%0,%1,%2,%3}, [%4];" \
        : "=r"(r0), "=r"(r1), "=r"(r2), "=r"(r3) : "r"(addr))
#define MMA16816(c, a, b0, b1) \
    asm volatile("mma.sync.aligned.m16n8k16.row.col.f32.bf16.bf16.f32 " \
        "{%0,%1,%2,%3}, {%4,%5,%6,%7}, {%8,%9}, {%0,%1,%2,%3};" \
        : "+f"((c)[0]), "+f"((c)[1]), "+f"((c)[2]), "+f"((c)[3]) \
        : "r"((a)[0]), "r"((a)[1]), "r"((a)[2]), "r"((a)[3]), "r"(b0), "r"(b1))

// ---------------- prep kernels ---------------------------------------------
__global__ void prep_b_kernel(const float* __restrict__ bih,
                              const float* __restrict__ bhh,
                              float* __restrict__ bsum) {
    int idx = blockIdx.x * 256 + threadIdx.x;
    if (idx < NGATE) bsum[idx] = bih[idx] + bhh[idx];
}

// batch may arrive as int32 (JAX default) or int64; detect on-device.
__global__ void seg_kernel(const void* __restrict__ batchv, int n,
                           int* __restrict__ seg) {
    const int*       w32 = (const int*)batchv;
    const long long* w64 = (const long long*)batchv;
    const bool is64 = (w32[n - 1] == 0);
    int b = blockIdx.x * 256 + threadIdx.x;
    if (b > BGRAPH) return;
    int lo = 0, hi = n;
    while (lo < hi) {
        int mid = (lo + hi) >> 1;
        long long v = is64 ? w64[mid] : (long long)w32[mid];
        if (v < (long long)b) lo = mid + 1; else hi = mid;
    }
    seg[b] = lo;
}

__global__ void init_zero_kernel(float* __restrict__ S, float* __restrict__ c) {
    int idx = blockIdx.x * 256 + threadIdx.x;
    if (idx < BGRAPH * KDIM) S[idx] = 0.f;
    else                     c[idx - BGRAPH * KDIM] = 0.f;
}

// ---------------- bf16x3 split-cat builders (row-major) ---------------------
// Weight rows: classes along Kcat: [0,1024):hi [1024,2048):hi [2048,3072):lo
__global__ void build_w_kernel(const float* __restrict__ Wa,
                               const float* __restrict__ Whh, int fold,
                               __nv_bfloat16* __restrict__ dst) {
    int idx = blockIdx.x * 256 + threadIdx.x;   // one per 8 elems
    int row = idx / (KCAT / 8);
    int j   = idx % (KCAT / 8);
    int kc0 = j * 8;
    int cls = kc0 >> 10;                        // 0:hi 1:hi 2:lo
    int k0  = kc0 & 1023;
    const float* wr = Wa + (size_t)row * 1024 + k0;
    const float* hr = Whh + (size_t)row * 512;
    unsigned short u[8];
#pragma unroll
    for (int q = 0; q < 8; q++) {
        float v = wr[q];
        int k = k0 + q;
        if (fold && k < 512) v += hr[k];
        __nv_bfloat16 h = __float2bfloat16(v);
        __nv_bfloat16 o = (cls < 2) ? h : __float2bfloat16(v - __bfloat162float(h));
        u[q] = __bfloat16_as_ushort(o);
    }
    uint4 pk;
    pk.x = (uint32_t)u[0] | ((uint32_t)u[1] << 16);
    pk.y = (uint32_t)u[2] | ((uint32_t)u[3] << 16);
    pk.z = (uint32_t)u[4] | ((uint32_t)u[5] << 16);
    pk.w = (uint32_t)u[6] | ((uint32_t)u[7] << 16);
    *(uint4*)(dst + (size_t)row * KCAT + kc0) = pk;
}

// Activation rows (per step): classes [0,1024):hi [1024,2048):lo [2048,3072):hi
__global__ void build_a_kernel(const float* __restrict__ S,
                               __nv_bfloat16* __restrict__ dst) {
    int idx = blockIdx.x * 256 + threadIdx.x;
    int row = idx / (KCAT / 8);
    int j   = idx % (KCAT / 8);
    int kc0 = j * 8;
    int cls = kc0 >> 10;                        // 0:hi 1:lo 2:hi
    int k0  = kc0 & 1023;
    const float* sr = S + (size_t)row * KDIM + k0;
    unsigned short u[8];
#pragma unroll
    for (int q = 0; q < 8; q++) {
        float v = sr[q];
        __nv_bfloat16 h = __float2bfloat16(v);
        __nv_bfloat16 o = (cls == 1) ? __float2bfloat16(v - __bfloat162float(h)) : h;
        u[q] = __bfloat16_as_ushort(o);
    }
    uint4 pk;
    pk.x = (uint32_t)u[0] | ((uint32_t)u[1] << 16);
    pk.y = (uint32_t)u[2] | ((uint32_t)u[3] << 16);
    pk.z = (uint32_t)u[4] | ((uint32_t)u[5] << 16);
    pk.w = (uint32_t)u[6] | ((uint32_t)u[7] << 16);
    *(uint4*)(dst + (size_t)row * KCAT + kc0) = pk;
}

// ---------------- mma.sync bf16 GEMM ----------------------------------------
// C[M,N] = Aext[M,KCAT] @ Bext[N,KCAT]^T + bias[N]  (opt ReLU)
// CTA tile 128(M) x 64(N) x 64(K bf16), 256 thr = 8 warps (4m x 2n), warp 32x32.
#define GBM 128
#define GBN 64
#define GBK 64
#define NKI (KCAT / GBK)      // 48 K-iterations
#define ASTAGE (GBM * GBK * 2)   // 16384 B
#define BSTAGE (GBN * GBK * 2)   // 8192 B

__global__ __launch_bounds__(256, 2)
void gemm_mma_kernel(const __nv_bfloat16* __restrict__ Aext,
                     const __nv_bfloat16* __restrict__ Bext,
                     const float* __restrict__ bias, float* __restrict__ C,
                     int ldc, int relu) {
    __shared__ __align__(128) char sA[2 * ASTAGE];   // 32 KB
    __shared__ __align__(128) char sB[2 * BSTAGE];   // 16 KB

    const int tid  = threadIdx.x;
    const int wid  = tid >> 5, lane = tid & 31;
    const int wm   = wid & 3;          // m-warp 0..3  -> m offset wm*32
    const int wn   = wid >> 2;         // n-warp 0..1  -> n offset wn*32
    const int bm   = blockIdx.y * GBM;
    const int bn   = blockIdx.x * GBN;

    const uint32_t sa = smem_u32(sA);
    const uint32_t sbb = smem_u32(sB);

    // cp.async source/dest mapping (16B chunks)
    // A: 128 rows x 128B = 8 chunks/row, 1024 chunks, 4 passes of 256
    // B: 64 rows  x 128B = 8 chunks/row,  512 chunks, 2 passes of 256
    const __nv_bfloat16* Abase = Aext + (size_t)bm * KCAT;
    const __nv_bfloat16* Bbase = Bext + (size_t)bn * KCAT;

    float acc[2][4][4] = {};

    // per-lane ldmatrix row precompute
    const int arow = wm * 32 + (lane & 15);          // + mi*16
    const int akb  = ((lane >> 4) & 1) * 16;
    const int nrow = wn * 32 + (lane & 7) + ((lane >> 4) & 1) * 8;  // + g*16
    const int nkb  = ((lane >> 3) & 1) * 16;

    // ---- prologue: stage 0 loads ----
#pragma unroll
    for (int p = 0; p < 4; p++) {
        int ch = p * 256 + tid, r = ch >> 3, c16 = ch & 7;
        cp16(sa + sw128(r * 128 + c16 * 16),
             Abase + (size_t)r * KCAT + c16 * 8);
    }
#pragma unroll
    for (int p = 0; p < 2; p++) {
        int ch = p * 256 + tid, r = ch >> 3, c16 = ch & 7;
        cp16(sbb + sw128(r * 128 + c16 * 16),
             Bbase + (size_t)r * KCAT + c16 * 8);
    }
    CP_COMMIT();

    for (int i = 0; i < NKI; i++) {
        const int cur = i & 1;
        if (i + 1 < NKI) {
            const int nxt = (i + 1) & 1;
            const __nv_bfloat16* An = Abase + (i + 1) * GBK;
            const __nv_bfloat16* Bn = Bbase + (i + 1) * GBK;
#pragma unroll
            for (int p = 0; p < 4; p++) {
                int ch = p * 256 + tid, r = ch >> 3, c16 = ch & 7;
                cp16(sa + nxt * ASTAGE + sw128(r * 128 + c16 * 16),
                     An + (size_t)r * KCAT + c16 * 8);
            }
#pragma unroll
            for (int p = 0; p < 2; p++) {
                int ch = p * 256 + tid, r = ch >> 3, c16 = ch & 7;
                cp16(sbb + nxt * BSTAGE + sw128(r * 128 + c16 * 16),
                     Bn + (size_t)r * KCAT + c16 * 8);
            }
            CP_COMMIT();
            CP_WAIT1();
        } else {
            CP_WAIT0();
        }
        __syncthreads();

        const uint32_t abase = sa + cur * ASTAGE;
        const uint32_t bbase = sbb + cur * BSTAGE;
#pragma unroll
        for (int kk = 0; kk < 4; kk++) {
            uint32_t af[2][4], bf[2][4];
#pragma unroll
            for (int mi = 0; mi < 2; mi++)
                LDSM_X4(af[mi][0], af[mi][1], af[mi][2], af[mi][3],
                        abase + sw128((arow + mi * 16) * 128 + kk * 32 + akb));
#pragma unroll
            for (int g = 0; g < 2; g++)
                LDSM_X4(bf[g][0], bf[g][1], bf[g][2], bf[g][3],
                        bbase + sw128((nrow + g * 16) * 128 + kk * 32 + nkb));
#pragma unroll
            for (int mi = 0; mi < 2; mi++)
#pragma unroll
                for (int nj = 0; nj < 4; nj++)
                    MMA16816(acc[mi][nj], af[mi],
                             bf[nj >> 1][(nj & 1) * 2], bf[nj >> 1][(nj & 1) * 2 + 1]);
        }
        __syncthreads();
    }

    // ---- epilogue ----
#pragma unroll
    for (int mi = 0; mi < 2; mi++) {
#pragma unroll
        for (int nj = 0; nj < 4; nj++) {
            int m0 = bm + wm * 32 + mi * 16 + (lane >> 2);
            int cn = bn + wn * 32 + nj * 8 + 2 * (lane & 3);
            float b0 = __ldg(bias + cn), b1 = __ldg(bias + cn + 1);
            float v0 = acc[mi][nj][0] + b0, v1 = acc[mi][nj][1] + b1;
            float v2 = acc[mi][nj][2] + b0, v3 = acc[mi][nj][3] + b1;
            if (relu) {
                v0 = fmaxf(v0, 0.f); v1 = fmaxf(v1, 0.f);
                v2 = fmaxf(v2, 0.f); v3 = fmaxf(v3, 0.f);
            }
            *(float2*)(C + (size_t)m0 * ldc + cn)       = make_float2(v0, v1);
            *(float2*)(C + (size_t)(m0 + 8) * ldc + cn) = make_float2(v2, v3);
        }
    }
}

// ---------------- LSTM cell elementwise ------------------------------------
__global__ __launch_bounds__(256)
void lstm_kernel(const float* __restrict__ z, float* __restrict__ c,
                 float* __restrict__ S) {
    int idx = blockIdx.x * 256 + threadIdx.x;
    int m = idx >> 9, d = idx & 511;
    const float* zr = z + (size_t)m * NGATE;
    float zi = zr[d], zf = zr[DIN + d], zg = zr[2 * DIN + d], zo = zr[3 * DIN + d];
    float si = 1.f / (1.f + __expf(-zi));
    float sf = 1.f / (1.f + __expf(-zf));
    float so = 1.f / (1.f + __expf(-zo));
    float cn = sf * c[idx] + si * tanhf(zg);
    c[idx] = cn;
    S[(size_t)m * KDIM + d] = so * tanhf(cn);
}

// ---------------- fused segment softmax attention --------------------------
__global__ __launch_bounds__(256)
void attn_kernel(const float* __restrict__ x, float* __restrict__ S,
                 const int* __restrict__ seg, float* __restrict__ escr) {
    __shared__ float  sq[DIN];
    __shared__ float4 sred[8 * 128];
    __shared__ float  swmax[8];
    __shared__ float  swden[8];
    __shared__ float  sgmax;

    const int b = blockIdx.x;
    const int tid = threadIdx.x;
    const int w = tid >> 5, lane = tid & 31;
    const int s = seg[b];
    const int e = seg[b + 1];

    for (int d = tid; d < DIN; d += 256) sq[d] = S[(size_t)b * KDIM + d];
    __syncthreads();

    const float4* q4 = (const float4*)sq;
    const float4 qa = q4[lane], qb = q4[32 + lane], qc = q4[64 + lane], qd = q4[96 + lane];

    float wmax = -INFINITY;
    for (int n = s + w; n < e; n += 8) {
        const float4* xv = (const float4*)(x + (size_t)n * DIN);
        float4 xa = xv[lane], xb = xv[32 + lane], xc = xv[64 + lane], xd = xv[96 + lane];
        float p = xa.x * qa.x + xa.y * qa.y + xa.z * qa.z + xa.w * qa.w;
        p += xb.x * qb.x + xb.y * qb.y + xb.z * qb.z + xb.w * qb.w;
        p += xc.x * qc.x + xc.y * qc.y + xc.z * qc.z + xc.w * qc.w;
        p += xd.x * qd.x + xd.y * qd.y + xd.z * qd.z + xd.w * qd.w;
#pragma unroll
        for (int off = 16; off > 0; off >>= 1)
            p += __shfl_xor_sync(0xffffffffu, p, off);
        if (lane == 0) escr[n] = p;
        wmax = fmaxf(wmax, p);
    }
    if (lane == 0) swmax[w] = wmax;
    __syncthreads();
    if (tid == 0) {
        float m = -INFINITY;
#pragma unroll
        for (int i = 0; i < 8; i++) m = fmaxf(m, swmax[i]);
        sgmax = m;
    }
    __syncthreads();
    const float gmax = sgmax;

    float4 aa = make_float4(0, 0, 0, 0), ab = aa, ac = aa, ad = aa;
    float den = 0.f;
    for (int n = s + w; n < e; n += 8) {
        float ex = __expf(escr[n] - gmax);
        const float4* xv = (const float4*)(x + (size_t)n * DIN);
        float4 xa = xv[lane], xb = xv[32 + lane], xc = xv[64 + lane], xd = xv[96 + lane];
        aa.x += ex * xa.x; aa.y += ex * xa.y; aa.z += ex * xa.z; aa.w += ex * xa.w;
        ab.x += ex * xb.x; ab.y += ex * xb.y; ab.z += ex * xb.z; ab.w += ex * xb.w;
        ac.x += ex * xc.x; ac.y += ex * xc.y; ac.z += ex * xc.z; ac.w += ex * xc.w;
        ad.x += ex * xd.x; ad.y += ex * xd.y; ad.z += ex * xd.z; ad.w += ex * xd.w;
        den += ex;
    }
    sred[w * 128 + lane]      = aa;
    sred[w * 128 + 32 + lane] = ab;
    sred[w * 128 + 64 + lane] = ac;
    sred[w * 128 + 96 + lane] = ad;
    if (lane == 0) swden[w] = den;
    __syncthreads();

    if (tid < 128) {
        float4 t = make_float4(0, 0, 0, 0);
#pragma unroll
        for (int ww = 0; ww < 8; ww++) {
            float4 v = sred[ww * 128 + tid];
            t.x += v.x; t.y += v.y; t.z += v.z; t.w += v.w;
        }
        float dtot = 0.f;
#pragma unroll
        for (int i = 0; i < 8; i++) dtot += swden[i];
        float inv = (e > s) ? (1.0f / dtot) : 0.f;
        t.x *= inv; t.y *= inv; t.z *= inv; t.w *= inv;
        ((float4*)(S + (size_t)b * KDIM + DIN))[tid] = t;
    }
}

// ---------------- launch ----------------------------------------------------
extern "C" void kernel_launch(void* const* d_in, const int* in_sizes, int n_in,
                              void* d_out, int out_size) {
    const float* x     = (const float*)d_in[0];
    const void*  batch = d_in[1];
    const float* Wih   = (const float*)d_in[2];
    const float* Whh   = (const float*)d_in[3];
    const float* bih   = (const float*)d_in[4];
    const float* bhh   = (const float*)d_in[5];
    const float* Wpost = (const float*)d_in[6];
    const float* bpost = (const float*)d_in[7];
    float*       out   = (float*)d_out;
    const int N = in_sizes[1];

    float *S, *c, *z, *bsum, *e;
    int* seg;
    __nv_bfloat16 *Aext, *Bext, *Pext;
    cudaGetSymbolAddress((void**)&S,    g_S);
    cudaGetSymbolAddress((void**)&c,    g_c);
    cudaGetSymbolAddress((void**)&z,    g_z);
    cudaGetSymbolAddress((void**)&bsum, g_bsum);
    cudaGetSymbolAddress((void**)&e,    g_e);
    cudaGetSymbolAddress((void**)&seg,  g_seg);
    cudaGetSymbolAddress((void**)&Aext, g_Aext);
    cudaGetSymbolAddress((void**)&Bext, g_Bext);
    cudaGetSymbolAddress((void**)&Pext, g_Pext);

    build_w_kernel<<<NGATE * (KCAT / 8) / 256, 256>>>(Wih, Whh, 1, Bext);
    build_w_kernel<<<DIN * (KCAT / 8) / 256, 256>>>(Wpost, Wpost, 0, Pext);
    prep_b_kernel<<<NGATE / 256, 256>>>(bih, bhh, bsum);
    seg_kernel<<<(BGRAPH + 1 + 255) / 256, 256>>>(batch, N, seg);
    init_zero_kernel<<<(BGRAPH * KDIM + BGRAPH * DIN) / 256, 256>>>(S, c);

    for (int t = 0; t < TSTEPS; t++) {
        build_a_kernel<<<BGRAPH * (KCAT / 8) / 256, 256>>>(S, Aext);
        // z = S @ Wcomb^T + bsum : grid (2048/64, 1024/128) = 32 x 8 = 256 CTAs
        gemm_mma_kernel<<<dim3(NGATE / GBN, BGRAPH / GBM), 256>>>(
            Aext, Bext, bsum, z, NGATE, 0);
        lstm_kernel<<<(BGRAPH * DIN) / 256, 256>>>(z, c, S);
        attn_kernel<<<BGRAPH, 256>>>(x, S, seg, e);
    }
    build_a_kernel<<<BGRAPH * (KCAT / 8) / 256, 256>>>(S, Aext);
    gemm_mma_kernel<<<dim3(DIN / GBN, BGRAPH / GBM), 256>>>(
        Aext, Pext, bpost, out, DIN, 1);
}

// round 12
// speedup vs baseline: 3.1333x; 1.3114x over previous
#include <cuda_runtime.h>
#include <cuda_bf16.h>
#include <math.h>
#include <stdint.h>

// Problem constants (fixed shapes from reference)
#define DIN    512
#define BGRAPH 1024
#define NGATE  2048   // 4*DIN
#define KDIM   1024   // 2*DIN  (state S = [h | r])
#define TSTEPS 6
#define KCAT   3072   // bf16x3 concatenated K

// ---------------- scratch (device globals; no allocation allowed) ----------
__device__ float g_bsum[NGATE];
__device__ float g_S[BGRAPH * KDIM];      // 4 MB  [h | r] state (fp32)
__device__ float g_c[BGRAPH * DIN];       // 2 MB  cell state
__device__ float g_z[BGRAPH * NGATE];     // 8 MB  pre-activation gates
__device__ int   g_seg[BGRAPH + 1];       // segment boundaries
// Plain row-major bf16 split-cat operands [rows][3072]:
// A classes: [0,1024):hi(S) [1024,2048):lo(S) [2048,3072):hi(S)
// W classes: [0,1024):hi(W) [1024,2048):hi(W) [2048,3072):lo(W)
__device__ __align__(128) __nv_bfloat16 g_Aext[BGRAPH * KCAT];  // 6 MB
__device__ __align__(128) __nv_bfloat16 g_Bext[NGATE * KCAT];   // 12 MB
__device__ __align__(128) __nv_bfloat16 g_Pext[DIN * KCAT];     // 3 MB

// ---------------- helpers ---------------------------------------------------
__device__ __forceinline__ uint32_t smem_u32(const void* p) {
    uint32_t a;
    asm("{ .reg .u64 t; cvta.to.shared.u64 t, %1; cvt.u32.u64 %0, t; }"
        : "=r"(a) : "l"(p));
    return a;
}
__device__ __forceinline__ uint32_t sw128(uint32_t off) {
    return off ^ ((off >> 3) & 0x70);
}
__device__ __forceinline__ void cp16(uint32_t dst, const void* src) {
    asm volatile("cp.async.cg.shared.global [%0], [%1], 16;"
                 :: "r"(dst), "l"(src));
}
#define CP_COMMIT() asm volatile("cp.async.commit_group;")
#define CP_WAIT1()  asm volatile("cp.async.wait_group 1;")
#define CP_WAIT0()  asm volatile("cp.async.wait_group 0;")
#define LDSM_X4(r0, r1, r2, r3, addr) \
    asm volatile("ldmatrix.sync.aligned.m8n8.x4.shared.b16 {%0,%1,%2,%3}, [%4];" \
        : "=r"(r0), "=r"(r1), "=r"(r2), "=r"(r3) : "r"(addr))
#define MMA16816(c, a, b0, b1) \
    asm volatile("mma.sync.aligned.m16n8k16.row.col.f32.bf16.bf16.f32 " \
        "{%0,%1,%2,%3}, {%4,%5,%6,%7}, {%8,%9}, {%0,%1,%2,%3};" \
        : "+f"((c)[0]), "+f"((c)[1]), "+f"((c)[2]), "+f"((c)[3]) \
        : "r"((a)[0]), "r"((a)[1]), "r"((a)[2]), "r"((a)[3]), "r"(b0), "r"(b1))

__device__ __forceinline__ unsigned short bf_hi(float v) {
    return __bfloat16_as_ushort(__float2bfloat16(v));
}
__device__ __forceinline__ unsigned short bf_lo(float v) {
    __nv_bfloat16 h = __float2bfloat16(v);
    return __bfloat16_as_ushort(__float2bfloat16(v - __bfloat162float(h)));
}

// ---------------- prep kernels ---------------------------------------------
__global__ void prep_b_kernel(const float* __restrict__ bih,
                              const float* __restrict__ bhh,
                              float* __restrict__ bsum) {
    int idx = blockIdx.x * 256 + threadIdx.x;
    if (idx < NGATE) bsum[idx] = bih[idx] + bhh[idx];
}

// Boundary-scatter segment build. batch arrives int32 (JAX default) or int64.
__global__ void seg_kernel(const void* __restrict__ batchv, int n,
                           int* __restrict__ seg) {
    const int*       w32 = (const int*)batchv;
    const long long* w64 = (const long long*)batchv;
    const bool is64 = (w32[n - 1] == 0);   // high word of int64 elem, else ~1023
    int i = blockIdx.x * 256 + threadIdx.x;
    if (i > n) return;
    long long bi = (i < n) ? (is64 ? w64[i] : (long long)w32[i])
                           : (long long)BGRAPH;
    long long bp = (i > 0) ? (is64 ? w64[i - 1] : (long long)w32[i - 1])
                           : (long long)-1;
    for (long long b = bp + 1; b <= bi; b++) seg[b] = i;
}

// Zero S (1M f32), c (0.5M f32), Aext (1.5M u32 words)
__global__ void init_zero_kernel(float* __restrict__ S, float* __restrict__ c,
                                 uint32_t* __restrict__ Aw) {
    int idx = blockIdx.x * 256 + threadIdx.x;   // < 3M
    if (idx < BGRAPH * KDIM)                 S[idx] = 0.f;
    else if (idx < BGRAPH * KDIM + BGRAPH * DIN)
        c[idx - BGRAPH * KDIM] = 0.f;
    else
        Aw[idx - (BGRAPH * KDIM + BGRAPH * DIN)] = 0u;
}

// Weight split-cat builder (built once).
__global__ void build_w_kernel(const float* __restrict__ Wa,
                               const float* __restrict__ Whh, int fold,
                               __nv_bfloat16* __restrict__ dst) {
    int idx = blockIdx.x * 256 + threadIdx.x;   // one per 8 elems
    int row = idx / (KCAT / 8);
    int j   = idx % (KCAT / 8);
    int kc0 = j * 8;
    int cls = kc0 >> 10;                        // 0:hi 1:hi 2:lo
    int k0  = kc0 & 1023;
    const float* wr = Wa + (size_t)row * 1024 + k0;
    const float* hr = Whh + (size_t)row * 512;
    unsigned short u[8];
#pragma unroll
    for (int q = 0; q < 8; q++) {
        float v = wr[q];
        int k = k0 + q;
        if (fold && k < 512) v += hr[k];
        u[q] = (cls < 2) ? bf_hi(v) : bf_lo(v);
    }
    uint4 pk;
    pk.x = (uint32_t)u[0] | ((uint32_t)u[1] << 16);
    pk.y = (uint32_t)u[2] | ((uint32_t)u[3] << 16);
    pk.z = (uint32_t)u[4] | ((uint32_t)u[5] << 16);
    pk.w = (uint32_t)u[6] | ((uint32_t)u[7] << 16);
    *(uint4*)(dst + (size_t)row * KCAT + kc0) = pk;
}

// ---------------- mma.sync bf16 GEMM ----------------------------------------
// C[M,N] = Aext[M,KCAT] @ Bext[N,KCAT]^T + bias[N]  (opt ReLU)
#define GBM 128
#define GBN 64
#define GBK 64
#define NKI (KCAT / GBK)         // 48 K-iterations
#define ASTAGE (GBM * GBK * 2)   // 16384 B
#define BSTAGE (GBN * GBK * 2)   // 8192 B

__global__ __launch_bounds__(256, 2)
void gemm_mma_kernel(const __nv_bfloat16* __restrict__ Aext,
                     const __nv_bfloat16* __restrict__ Bext,
                     const float* __restrict__ bias, float* __restrict__ C,
                     int ldc, int relu) {
    __shared__ __align__(128) char sA[2 * ASTAGE];   // 32 KB
    __shared__ __align__(128) char sB[2 * BSTAGE];   // 16 KB

    const int tid  = threadIdx.x;
    const int wid  = tid >> 5, lane = tid & 31;
    const int wm   = wid & 3;
    const int wn   = wid >> 2;
    const int bm   = blockIdx.y * GBM;
    const int bn   = blockIdx.x * GBN;

    const uint32_t sa = smem_u32(sA);
    const uint32_t sbb = smem_u32(sB);

    const __nv_bfloat16* Abase = Aext + (size_t)bm * KCAT;
    const __nv_bfloat16* Bbase = Bext + (size_t)bn * KCAT;

    float acc[2][4][4] = {};

    const int arow = wm * 32 + (lane & 15);
    const int akb  = ((lane >> 4) & 1) * 16;
    const int nrow = wn * 32 + (lane & 7) + ((lane >> 4) & 1) * 8;
    const int nkb  = ((lane >> 3) & 1) * 16;

#pragma unroll
    for (int p = 0; p < 4; p++) {
        int ch = p * 256 + tid, r = ch >> 3, c16 = ch & 7;
        cp16(sa + sw128(r * 128 + c16 * 16),
             Abase + (size_t)r * KCAT + c16 * 8);
    }
#pragma unroll
    for (int p = 0; p < 2; p++) {
        int ch = p * 256 + tid, r = ch >> 3, c16 = ch & 7;
        cp16(sbb + sw128(r * 128 + c16 * 16),
             Bbase + (size_t)r * KCAT + c16 * 8);
    }
    CP_COMMIT();

    for (int i = 0; i < NKI; i++) {
        const int cur = i & 1;
        if (i + 1 < NKI) {
            const int nxt = (i + 1) & 1;
            const __nv_bfloat16* An = Abase + (i + 1) * GBK;
            const __nv_bfloat16* Bn = Bbase + (i + 1) * GBK;
#pragma unroll
            for (int p = 0; p < 4; p++) {
                int ch = p * 256 + tid, r = ch >> 3, c16 = ch & 7;
                cp16(sa + nxt * ASTAGE + sw128(r * 128 + c16 * 16),
                     An + (size_t)r * KCAT + c16 * 8);
            }
#pragma unroll
            for (int p = 0; p < 2; p++) {
                int ch = p * 256 + tid, r = ch >> 3, c16 = ch & 7;
                cp16(sbb + nxt * BSTAGE + sw128(r * 128 + c16 * 16),
                     Bn + (size_t)r * KCAT + c16 * 8);
            }
            CP_COMMIT();
            CP_WAIT1();
        } else {
            CP_WAIT0();
        }
        __syncthreads();

        const uint32_t abase = sa + cur * ASTAGE;
        const uint32_t bbase = sbb + cur * BSTAGE;
#pragma unroll
        for (int kk = 0; kk < 4; kk++) {
            uint32_t af[2][4], bf[2][4];
#pragma unroll
            for (int mi = 0; mi < 2; mi++)
                LDSM_X4(af[mi][0], af[mi][1], af[mi][2], af[mi][3],
                        abase + sw128((arow + mi * 16) * 128 + kk * 32 + akb));
#pragma unroll
            for (int g = 0; g < 2; g++)
                LDSM_X4(bf[g][0], bf[g][1], bf[g][2], bf[g][3],
                        bbase + sw128((nrow + g * 16) * 128 + kk * 32 + nkb));
#pragma unroll
            for (int mi = 0; mi < 2; mi++)
#pragma unroll
                for (int nj = 0; nj < 4; nj++)
                    MMA16816(acc[mi][nj], af[mi],
                             bf[nj >> 1][(nj & 1) * 2], bf[nj >> 1][(nj & 1) * 2 + 1]);
        }
        __syncthreads();
    }

#pragma unroll
    for (int mi = 0; mi < 2; mi++) {
#pragma unroll
        for (int nj = 0; nj < 4; nj++) {
            int m0 = bm + wm * 32 + mi * 16 + (lane >> 2);
            int cn = bn + wn * 32 + nj * 8 + 2 * (lane & 3);
            float b0 = __ldg(bias + cn), b1 = __ldg(bias + cn + 1);
            float v0 = acc[mi][nj][0] + b0, v1 = acc[mi][nj][1] + b1;
            float v2 = acc[mi][nj][2] + b0, v3 = acc[mi][nj][3] + b1;
            if (relu) {
                v0 = fmaxf(v0, 0.f); v1 = fmaxf(v1, 0.f);
                v2 = fmaxf(v2, 0.f); v3 = fmaxf(v3, 0.f);
            }
            *(float2*)(C + (size_t)m0 * ldc + cn)       = make_float2(v0, v1);
            *(float2*)(C + (size_t)(m0 + 8) * ldc + cn) = make_float2(v2, v3);
        }
    }
}

// ---------------- LSTM cell + fused bf16x3 h-export -------------------------
// 2 elems/thread. Writes h to S (fp32) and its hi/lo/hi classes into Aext.
__global__ __launch_bounds__(256)
void lstm_kernel(const float* __restrict__ z, float* __restrict__ c,
                 float* __restrict__ S, __nv_bfloat16* __restrict__ Aext) {
    int T = blockIdx.x * 256 + threadIdx.x;     // < 262144
    int m = T >> 8, d = (T & 255) * 2;
    const float* zr = z + (size_t)m * NGATE;
    float2 zi = *(const float2*)(zr + d);
    float2 zf = *(const float2*)(zr + 512 + d);
    float2 zg = *(const float2*)(zr + 1024 + d);
    float2 zo = *(const float2*)(zr + 1536 + d);
    float2 cc = *(float2*)(c + (size_t)m * DIN + d);

    float si0 = 1.f / (1.f + __expf(-zi.x)), si1 = 1.f / (1.f + __expf(-zi.y));
    float sf0 = 1.f / (1.f + __expf(-zf.x)), sf1 = 1.f / (1.f + __expf(-zf.y));
    float so0 = 1.f / (1.f + __expf(-zo.x)), so1 = 1.f / (1.f + __expf(-zo.y));
    float cn0 = sf0 * cc.x + si0 * tanhf(zg.x);
    float cn1 = sf1 * cc.y + si1 * tanhf(zg.y);
    float h0 = so0 * tanhf(cn0);
    float h1 = so1 * tanhf(cn1);

    *(float2*)(c + (size_t)m * DIN + d) = make_float2(cn0, cn1);
    *(float2*)(S + (size_t)m * KDIM + d) = make_float2(h0, h1);

    __nv_bfloat16* ar = Aext + (size_t)m * KCAT;
    uint32_t hi = (uint32_t)bf_hi(h0) | ((uint32_t)bf_hi(h1) << 16);
    uint32_t lo = (uint32_t)bf_lo(h0) | ((uint32_t)bf_lo(h1) << 16);
    *(uint32_t*)(ar + d)        = hi;
    *(uint32_t*)(ar + 1024 + d) = lo;
    *(uint32_t*)(ar + 2048 + d) = hi;
}

// ---------------- online-softmax segment attention (single x pass) ---------
__global__ __launch_bounds__(256)
void attn_kernel(const float* __restrict__ x, float* __restrict__ S,
                 const int* __restrict__ seg, __nv_bfloat16* __restrict__ Aext) {
    __shared__ float  sq[DIN];
    __shared__ float4 sred[8 * 128];   // per-warp 512-dim accumulators
    __shared__ float  swm[8];          // per-warp running max
    __shared__ float  swd[8];          // per-warp denom

    const int b = blockIdx.x;
    const int tid = threadIdx.x;
    const int w = tid >> 5, lane = tid & 31;
    const int s = seg[b];
    const int e = seg[b + 1];

    for (int d = tid; d < DIN; d += 256) sq[d] = S[(size_t)b * KDIM + d];  // q=h
    __syncthreads();

    const float4* q4 = (const float4*)sq;
    const float4 qa = q4[lane], qb = q4[32 + lane], qc = q4[64 + lane], qd = q4[96 + lane];

    float m = -INFINITY, den = 0.f;
    float4 aa = make_float4(0, 0, 0, 0), ab = aa, ac = aa, ad = aa;

    for (int n = s + w; n < e; n += 8) {
        const float4* xv = (const float4*)(x + (size_t)n * DIN);
        float4 xa = xv[lane], xb = xv[32 + lane], xc = xv[64 + lane], xd = xv[96 + lane];
        float p = xa.x * qa.x + xa.y * qa.y + xa.z * qa.z + xa.w * qa.w;
        p += xb.x * qb.x + xb.y * qb.y + xb.z * qb.z + xb.w * qb.w;
        p += xc.x * qc.x + xc.y * qc.y + xc.z * qc.z + xc.w * qc.w;
        p += xd.x * qd.x + xd.y * qd.y + xd.z * qd.z + xd.w * qd.w;
#pragma unroll
        for (int off = 16; off > 0; off >>= 1)
            p += __shfl_xor_sync(0xffffffffu, p, off);
        // online rescale (x row is already in registers — no second pass)
        float mn = fmaxf(m, p);
        float sc = __expf(m - mn);     // m=-inf first iter -> 0
        float ex = __expf(p - mn);
        den = den * sc + ex;
        aa.x = aa.x * sc + ex * xa.x; aa.y = aa.y * sc + ex * xa.y;
        aa.z = aa.z * sc + ex * xa.z; aa.w = aa.w * sc + ex * xa.w;
        ab.x = ab.x * sc + ex * xb.x; ab.y = ab.y * sc + ex * xb.y;
        ab.z = ab.z * sc + ex * xb.z; ab.w = ab.w * sc + ex * xb.w;
        ac.x = ac.x * sc + ex * xc.x; ac.y = ac.y * sc + ex * xc.y;
        ac.z = ac.z * sc + ex * xc.z; ac.w = ac.w * sc + ex * xc.w;
        ad.x = ad.x * sc + ex * xd.x; ad.y = ad.y * sc + ex * xd.y;
        ad.z = ad.z * sc + ex * xd.z; ad.w = ad.w * sc + ex * xd.w;
        m = mn;
    }
    sred[w * 128 + lane]      = aa;
    sred[w * 128 + 32 + lane] = ab;
    sred[w * 128 + 64 + lane] = ac;
    sred[w * 128 + 96 + lane] = ad;
    if (lane == 0) { swm[w] = m; swd[w] = den; }
    __syncthreads();

    if (tid < 128) {
        float4 t = make_float4(0, 0, 0, 0);
        if (e > s) {
            float M = -INFINITY;
#pragma unroll
            for (int i = 0; i < 8; i++) M = fmaxf(M, swm[i]);
            float dtot = 0.f;
#pragma unroll
            for (int ww = 0; ww < 8; ww++) {
                float ws = __expf(swm[ww] - M);   // -inf warp -> 0
                float4 v = sred[ww * 128 + tid];
                t.x += ws * v.x; t.y += ws * v.y;
                t.z += ws * v.z; t.w += ws * v.w;
                dtot += ws * swd[ww];
            }
            float inv = 1.0f / dtot;
            t.x *= inv; t.y *= inv; t.z *= inv; t.w *= inv;
        }
        ((float4*)(S + (size_t)b * KDIM + DIN))[tid] = t;  // r fp32

        // fused bf16x3 r-export into Aext columns 512+4*tid (+class offsets)
        __nv_bfloat16* ar = Aext + (size_t)b * KCAT + 512 + 4 * tid;
        uint2 hi, lo;
        hi.x = (uint32_t)bf_hi(t.x) | ((uint32_t)bf_hi(t.y) << 16);
        hi.y = (uint32_t)bf_hi(t.z) | ((uint32_t)bf_hi(t.w) << 16);
        lo.x = (uint32_t)bf_lo(t.x) | ((uint32_t)bf_lo(t.y) << 16);
        lo.y = (uint32_t)bf_lo(t.z) | ((uint32_t)bf_lo(t.w) << 16);
        *(uint2*)(ar)        = hi;
        *(uint2*)(ar + 1024) = lo;
        *(uint2*)(ar + 2048) = hi;
    }
}

// ---------------- launch ----------------------------------------------------
extern "C" void kernel_launch(void* const* d_in, const int* in_sizes, int n_in,
                              void* d_out, int out_size) {
    const float* x     = (const float*)d_in[0];
    const void*  batch = d_in[1];
    const float* Wih   = (const float*)d_in[2];
    const float* Whh   = (const float*)d_in[3];
    const float* bih   = (const float*)d_in[4];
    const float* bhh   = (const float*)d_in[5];
    const float* Wpost = (const float*)d_in[6];
    const float* bpost = (const float*)d_in[7];
    float*       out   = (float*)d_out;
    const int N = in_sizes[1];

    float *S, *c, *z, *bsum;
    int* seg;
    __nv_bfloat16 *Aext, *Bext, *Pext;
    cudaGetSymbolAddress((void**)&S,    g_S);
    cudaGetSymbolAddress((void**)&c,    g_c);
    cudaGetSymbolAddress((void**)&z,    g_z);
    cudaGetSymbolAddress((void**)&bsum, g_bsum);
    cudaGetSymbolAddress((void**)&seg,  g_seg);
    cudaGetSymbolAddress((void**)&Aext, g_Aext);
    cudaGetSymbolAddress((void**)&Bext, g_Bext);
    cudaGetSymbolAddress((void**)&Pext, g_Pext);

    build_w_kernel<<<NGATE * (KCAT / 8) / 256, 256>>>(Wih, Whh, 1, Bext);
    build_w_kernel<<<DIN * (KCAT / 8) / 256, 256>>>(Wpost, Wpost, 0, Pext);
    prep_b_kernel<<<NGATE / 256, 256>>>(bih, bhh, bsum);
    seg_kernel<<<(N + 256) / 256, 256>>>(batch, N, seg);
    // zero S + c + Aext (3M 4-byte words)
    init_zero_kernel<<<(BGRAPH * KDIM + BGRAPH * DIN +
                        BGRAPH * KCAT / 2) / 256, 256>>>(S, c, (uint32_t*)Aext);

    for (int t = 0; t < TSTEPS; t++) {
        gemm_mma_kernel<<<dim3(NGATE / GBN, BGRAPH / GBM), 256>>>(
            Aext, Bext, bsum, z, NGATE, 0);
        lstm_kernel<<<(BGRAPH * DIN / 2) / 256, 256>>>(z, c, S, Aext);
        attn_kernel<<<BGRAPH, 256>>>(x, S, seg, Aext);
    }
    gemm_mma_kernel<<<dim3(DIN / GBN, BGRAPH / GBM), 256>>>(
        Aext, Pext, bpost, out, DIN, 1);
}